// round 1
// baseline (speedup 1.0000x reference)
#include <cuda_runtime.h>

#define BB 4
#define NPTS 2048
#define HH 128
#define WW 128
#define SPLITS 16
#define KCH (NPTS / SPLITS)   // 128 atoms per split

// Scratch (no allocations allowed in kernel_launch)
__device__ float g_fx[BB * NPTS * WW];            // 4 MB: exp(-(w-px)^2/4.5)
__device__ float g_fy[BB * NPTS * HH];            // 4 MB: exp(-(h-py)^2/4.5)
__device__ float g_part[SPLITS * BB * HH * WW];   // 4 MB: split-K partials

// ---------------------------------------------------------------------------
// Kernel 1: factor tables. One thread per (b, n, w); computes Fx and Fy entry.
// ---------------------------------------------------------------------------
__global__ void factors_kernel(const float* __restrict__ x,
                               const float* __restrict__ rot) {
    int idx = blockIdx.x * blockDim.x + threadIdx.x;
    if (idx >= BB * NPTS * WW) return;
    int w  = idx & 127;          // pixel coordinate (also reused as h for Fy)
    int bn = idx >> 7;           // b*NPTS + n
    int b  = bn >> 11;           // NPTS = 2048

    const float* xp = x + bn * 3;
    float x0 = xp[0], x1 = xp[1], x2 = xp[2];
    const float* R = rot + b * 9;

    const float scale = 51.2f;   // min(H,W)/2 * 0.8
    float px = fmaf(R[0], x0, fmaf(R[1], x1, R[2] * x2)) * scale + 64.0f;
    float py = fmaf(R[3], x0, fmaf(R[4], x1, R[5] * x2)) * scale + 64.0f;

    float dx = (float)w - px;
    float dy = (float)w - py;
    float qx = dx * dx;
    float qy = dy * dy;
    const float c = -1.0f / 4.5f;           // -1/(2*sigma^2), sigma=1.5
    // cutoff at d^2 >= 144 -> exp(-32) ~ 1.3e-14, negligible vs 1e-3 gate
    g_fx[idx] = (qx < 144.0f) ? __expf(qx * c) : 0.0f;
    g_fy[idx] = (qy < 144.0f) ? __expf(qy * c) : 0.0f;
}

// ---------------------------------------------------------------------------
// Kernel 2: split-K GEMM.  clean[b] += Fy_chunk^T (128x128) * Fx_chunk (128x128)
// grid = (SPLITS, BB), 256 threads, 8x8 register tile per thread.
// ---------------------------------------------------------------------------
__global__ void __launch_bounds__(256, 1) gemm_kernel() {
    int s = blockIdx.x;
    int b = blockIdx.y;
    const float* fx = g_fx + (b * NPTS + s * KCH) * WW;  // [KCH][W]
    const float* fy = g_fy + (b * NPTS + s * KCH) * HH;  // [KCH][H]

    __shared__ float sy[16][128];
    __shared__ float sx[16][128];

    int tid = threadIdx.x;
    int tx = tid & 15;        // 16 col-groups
    int ty = tid >> 4;        // 16 row-groups

    float acc[8][8];
#pragma unroll
    for (int i = 0; i < 8; i++)
#pragma unroll
        for (int j = 0; j < 8; j++) acc[i][j] = 0.0f;

    for (int k0 = 0; k0 < KCH; k0 += 16) {
        // Load two 16x128 tiles: 512 float4 per tile, 256 threads x 2 each.
#pragma unroll
        for (int i = 0; i < 2; i++) {
            int e    = tid + i * 256;   // 0..511
            int kk   = e >> 5;          // row within tile (16 rows of 32 float4)
            int col4 = e & 31;
            ((float4*)sy[kk])[col4] = ((const float4*)(fy + (k0 + kk) * HH))[col4];
            ((float4*)sx[kk])[col4] = ((const float4*)(fx + (k0 + kk) * WW))[col4];
        }
        __syncthreads();

#pragma unroll
        for (int kk = 0; kk < 16; kk++) {
            float yv[8], xv[8];
            *(float4*)&yv[0] = *(float4*)&sy[kk][ty * 4];
            *(float4*)&yv[4] = *(float4*)&sy[kk][64 + ty * 4];
            *(float4*)&xv[0] = *(float4*)&sx[kk][tx * 4];
            *(float4*)&xv[4] = *(float4*)&sx[kk][64 + tx * 4];
#pragma unroll
            for (int i = 0; i < 8; i++)
#pragma unroll
                for (int j = 0; j < 8; j++)
                    acc[i][j] = fmaf(yv[i], xv[j], acc[i][j]);
        }
        __syncthreads();
    }

    float* out = g_part + (s * BB + b) * (HH * WW);
#pragma unroll
    for (int i = 0; i < 8; i++) {
        int h = (i < 4) ? (ty * 4 + i) : (64 + ty * 4 + (i - 4));
#pragma unroll
        for (int jj = 0; jj < 2; jj++) {
            int w = (jj == 0) ? (tx * 4) : (64 + tx * 4);
            float4 v = make_float4(acc[i][jj * 4 + 0], acc[i][jj * 4 + 1],
                                   acc[i][jj * 4 + 2], acc[i][jj * 4 + 3]);
            *(float4*)&out[h * WW + w] = v;
        }
    }
}

// ---------------------------------------------------------------------------
// Kernel 3: reduce partials, add noise, emit (noisy, rot, clean) flattened.
// ---------------------------------------------------------------------------
__global__ void combine_kernel(const float* __restrict__ noise,
                               const float* __restrict__ rot,
                               float* __restrict__ out) {
    int t = blockIdx.x * blockDim.x + threadIdx.x;
    if (t >= BB * HH * WW) return;
    float s = 0.0f;
#pragma unroll
    for (int i = 0; i < SPLITS; i++) s += g_part[i * (BB * HH * WW) + t];
    const int IMG = BB * HH * WW;           // 65536
    out[t] = fmaf(noise[t], 0.1f, s);       // noisy
    out[IMG + 36 + t] = s;                  // clean
    if (t < 36) out[IMG + t] = rot[t];      // rot_matrices passthrough
}

// ---------------------------------------------------------------------------
extern "C" void kernel_launch(void* const* d_in, const int* in_sizes, int n_in,
                              void* d_out, int out_size) {
    const float* x     = (const float*)d_in[0];  // (4,2048,3)
    const float* rot   = (const float*)d_in[1];  // (4,3,3)
    const float* noise = (const float*)d_in[2];  // (4,128,128)
    float* out = (float*)d_out;

    factors_kernel<<<(BB * NPTS * WW + 255) / 256, 256>>>(x, rot);

    dim3 grid(SPLITS, BB);
    gemm_kernel<<<grid, 256>>>();

    combine_kernel<<<(BB * HH * WW + 255) / 256, 256>>>(noise, rot, out);
}

// round 2
// speedup vs baseline: 1.4810x; 1.4810x over previous
#include <cuda_runtime.h>

#define BB 4
#define NPTS 2048
#define HH 128
#define WW 128
#define SPLITS 32
#define KCH (NPTS / SPLITS)   // 64 atoms per block
#define CHUNK 32              // atoms resident in shared at once
#define IMG (BB * HH * WW)    // 65536

// Split-K partials (no allocations allowed): 32 * 64KB = 8 MB
__device__ float g_part[SPLITS * BB * HH * WW];

// ---------------------------------------------------------------------------
// Fused kernel: per block (split s, batch b), compute factor tiles for its
// 64 atoms directly in shared (rotation + truncated Gaussian), then
// accumulate the 128x128 outer-product GEMM with 8x8 register tiles.
// ---------------------------------------------------------------------------
__global__ void __launch_bounds__(256) fused_kernel(const float* __restrict__ x,
                                                    const float* __restrict__ rot) {
    int s = blockIdx.x;
    int b = blockIdx.y;

    __shared__ float sfy[CHUNK][128];
    __shared__ float sfx[CHUNK][128];
    __shared__ float spx[CHUNK];
    __shared__ float spy[CHUNK];

    int tid = threadIdx.x;
    int tx = tid & 15;        // 16 col-groups
    int ty = tid >> 4;        // 16 row-groups

    // Rotation rows 0,1 (broadcast loads, L1-resident)
    const float* R = rot + b * 9;
    float R0 = R[0], R1 = R[1], R2 = R[2];
    float R3 = R[3], R4 = R[4], R5 = R[5];

    float acc[8][8];
#pragma unroll
    for (int i = 0; i < 8; i++)
#pragma unroll
        for (int j = 0; j < 8; j++) acc[i][j] = 0.0f;

    for (int c = 0; c < KCH / CHUNK; c++) {
        // --- Phase A: project this chunk's atoms (32 threads) ---
        if (tid < CHUNK) {
            int atom = b * NPTS + s * KCH + c * CHUNK + tid;
            const float* xp = x + atom * 3;
            float x0 = xp[0], x1 = xp[1], x2 = xp[2];
            const float scale = 51.2f;   // min(H,W)/2 * 0.8
            spx[tid] = fmaf(R0, x0, fmaf(R1, x1, R2 * x2)) * scale + 64.0f;
            spy[tid] = fmaf(R3, x0, fmaf(R4, x1, R5 * x2)) * scale + 64.0f;
        }
        __syncthreads();

        // --- Phase B: factor tables into shared. 32x128 entries per table,
        //     256 threads -> 16 (atom,pixel) pairs each; both tables per pair.
        //     Cutoff d^2 >= 144 (exp(-32) ~ 1e-14) skips MUFU for ~3/4 warps.
        const float cexp = -0.22222222f;  // -1/(2*1.5^2)
#pragma unroll 4
        for (int i = 0; i < 16; i++) {
            int e = tid + i * 256;        // 0..4095
            int a = e >> 7;
            int p = e & 127;
            float fp = (float)p;
            float dx = fp - spx[a];
            float dy = fp - spy[a];
            float qx = dx * dx;
            float qy = dy * dy;
            sfx[a][p] = (qx < 144.0f) ? __expf(qx * cexp) : 0.0f;
            sfy[a][p] = (qy < 144.0f) ? __expf(qy * cexp) : 0.0f;
        }
        __syncthreads();

        // --- Phase C: rank-32 update, 8x8 register tile per thread ---
#pragma unroll 8
        for (int kk = 0; kk < CHUNK; kk++) {
            float yv[8], xv[8];
            *(float4*)&yv[0] = *(float4*)&sfy[kk][ty * 4];
            *(float4*)&yv[4] = *(float4*)&sfy[kk][64 + ty * 4];
            *(float4*)&xv[0] = *(float4*)&sfx[kk][tx * 4];
            *(float4*)&xv[4] = *(float4*)&sfx[kk][64 + tx * 4];
#pragma unroll
            for (int i = 0; i < 8; i++)
#pragma unroll
                for (int j = 0; j < 8; j++)
                    acc[i][j] = fmaf(yv[i], xv[j], acc[i][j]);
        }
        __syncthreads();   // protect shared before next chunk overwrites
    }

    float* out = g_part + (s * BB + b) * (HH * WW);
#pragma unroll
    for (int i = 0; i < 8; i++) {
        int h = (i < 4) ? (ty * 4 + i) : (64 + ty * 4 + (i - 4));
#pragma unroll
        for (int jj = 0; jj < 2; jj++) {
            int w = (jj == 0) ? (tx * 4) : (64 + tx * 4);
            float4 v = make_float4(acc[i][jj * 4 + 0], acc[i][jj * 4 + 1],
                                   acc[i][jj * 4 + 2], acc[i][jj * 4 + 3]);
            *(float4*)&out[h * WW + w] = v;
        }
    }
}

// ---------------------------------------------------------------------------
// Combine: float4 reduction of 32 partial slices, add noise, emit
// (noisy[65536], rot[36], clean[65536]) into flat output.
// Note: clean base offset 65536+36 = 65572 is divisible by 4 -> float4 OK.
// ---------------------------------------------------------------------------
__global__ void combine_kernel(const float* __restrict__ noise,
                               const float* __restrict__ rot,
                               float* __restrict__ out) {
    int t = blockIdx.x * blockDim.x + threadIdx.x;   // 0 .. IMG/4
    if (t >= IMG / 4) return;
    const float4* part4 = (const float4*)g_part;
    float4 s = make_float4(0.f, 0.f, 0.f, 0.f);
#pragma unroll
    for (int i = 0; i < SPLITS; i++) {
        float4 v = part4[i * (IMG / 4) + t];
        s.x += v.x; s.y += v.y; s.z += v.z; s.w += v.w;
    }
    float4 nz = ((const float4*)noise)[t];
    float4 noisy = make_float4(fmaf(nz.x, 0.1f, s.x), fmaf(nz.y, 0.1f, s.y),
                               fmaf(nz.z, 0.1f, s.z), fmaf(nz.w, 0.1f, s.w));
    ((float4*)out)[t] = noisy;                       // noisy
    *(float4*)&out[IMG + 36 + t * 4] = s;            // clean
    if (t < 36) out[IMG + t] = rot[t];               // rot passthrough
}

// ---------------------------------------------------------------------------
extern "C" void kernel_launch(void* const* d_in, const int* in_sizes, int n_in,
                              void* d_out, int out_size) {
    const float* x     = (const float*)d_in[0];  // (4,2048,3)
    const float* rot   = (const float*)d_in[1];  // (4,3,3)
    const float* noise = (const float*)d_in[2];  // (4,128,128)
    float* out = (float*)d_out;

    dim3 grid(SPLITS, BB);
    fused_kernel<<<grid, 256>>>(x, rot);

    combine_kernel<<<(IMG / 4 + 255) / 256, 256>>>(noise, rot, out);
}